// round 14
// baseline (speedup 1.0000x reference)
#include <cuda_runtime.h>
#include <cuda_bf16.h>
#include <cstdint>

#define B_   256
#define T_   250
#define NIN  700
#define NHID 512
#define NOUT 20
#define KPAD 2816          // 4*NIN = 2800 padded to 128*22 (fp8 bytes)
#define NSTG 22            // K stages of 128 bytes
#define WSCALE 64.0f       // weight pre-scale into e4m3 normal range

// ---------------- scratch (static __device__, no runtime alloc) -------------
__device__ __nv_bfloat16 g_iin[(size_t)B_ * T_ * NHID];  // [B*T][H] bf16
__device__ uint8_t g_w8[(size_t)NHID * KPAD];            // [h][kk] e4m3, kk=4n+v
__device__ float   g_wrecT[NHID * NHID];                 // w_rec^T
__device__ int     g_flag[B_];                           // per-batch spike flag
__device__ int     g_cnt[B_];                            // per-batch pending-CTA count

// ---------------- helpers ----------------------------------------------------
__device__ __forceinline__ uint32_t smem_u32(const void* p) {
    uint32_t a;
    asm("{ .reg .u64 t; cvta.to.shared.u64 t, %1; cvt.u32.u64 %0, t; }"
        : "=r"(a) : "l"(p));
    return a;
}
__device__ __forceinline__ uint32_t pack_e4m3_4(float f0, float f1, float f2, float f3) {
    uint16_t lo, hi;  // d<7:0> = cvt(src2), d<15:8> = cvt(src1)
    asm("cvt.rn.satfinite.e4m3x2.f32 %0, %1, %2;" : "=h"(lo) : "f"(f1), "f"(f0));
    asm("cvt.rn.satfinite.e4m3x2.f32 %0, %1, %2;" : "=h"(hi) : "f"(f3), "f"(f2));
    return (uint32_t)lo | ((uint32_t)hi << 16);   // bytes f0,f1,f2,f3 (k-ascending)
}
__device__ __forceinline__ void ldmx4(uint32_t* r, uint32_t addr) {
    asm volatile("ldmatrix.sync.aligned.m8n8.x4.shared.b16 {%0,%1,%2,%3}, [%4];"
                 : "=r"(r[0]), "=r"(r[1]), "=r"(r[2]), "=r"(r[3]) : "r"(addr));
}
__device__ __forceinline__ void mma_e4m3(float* c, const uint32_t* a,
                                         uint32_t b0, uint32_t b1) {
    asm volatile(
        "mma.sync.aligned.m16n8k32.row.col.f32.e4m3.e4m3.f32 "
        "{%0,%1,%2,%3}, {%4,%5,%6,%7}, {%8,%9}, {%0,%1,%2,%3};"
        : "+f"(c[0]), "+f"(c[1]), "+f"(c[2]), "+f"(c[3])
        : "r"(a[0]), "r"(a[1]), "r"(a[2]), "r"(a[3]), "r"(b0), "r"(b1));
}

// ---------------- prep kernels ----------------------------------------------
__global__ void prep_w8_kernel(const float* __restrict__ wk, const float* __restrict__ d1,
                               const float* __restrict__ d2, const float* __restrict__ d3) {
    int i = blockIdx.x * blockDim.x + threadIdx.x;
    if (i >= NHID * 704) return;
    int h = i / 704, n = i % 704;
    uint32_t w = 0;
    if (n < NIN)
        w = pack_e4m3_4(wk[h * NIN + n] * WSCALE, d1[h * NIN + n] * WSCALE,
                        d2[h * NIN + n] * WSCALE, d3[h * NIN + n] * WSCALE);
    *(uint32_t*)&g_w8[(size_t)h * KPAD + 4 * n] = w;
}
__global__ void prep_wrect_kernel(const float* __restrict__ wrec) {
    int i = blockIdx.x * blockDim.x + threadIdx.x;
    if (i < B_) {
        g_flag[i] = 0;
        // batch i covered by m-tiles [250i/128, (250i+249)/128], x4 n-tiles
        int mLo = (250 * i) >> 7, mHi = (250 * i + 249) >> 7;
        g_cnt[i] = (mHi - mLo + 1) * 4;
    }
    if (i >= NHID * NHID) return;
    int h = i % NHID, j = i / NHID;
    g_wrecT[j * NHID + h] = wrec[h * NHID + j];
}

// ---------------- fused per-batch detection ----------------------------------
// Before the first spike, hidden dynamics are exactly per-(b,h) independent.
// A spike exists iff max_t v_t > 1 for some h. 256 threads = 256 h-pairs.
// On no-spike, writes the batch's zero outputs directly.
__device__ void detect_batch(int b, float* out) {
    __shared__ int sflag;
    __syncthreads();
    if (threadIdx.x == 0) sflag = 0;
    __syncthreads();
    const int pr = threadIdx.x;
    const __nv_bfloat162* iin =
        (const __nv_bfloat162*)(g_iin + (size_t)b * T_ * NHID) + pr;
    float v0 = 0.f, v1 = 0.f, vmax = -1.f;
#pragma unroll 10
    for (int t = 0; t < T_; t++) {
        float2 f = __bfloat1622float2(iin[(size_t)t * (NHID / 2)]);
        v0 = 0.95f * v0 + 0.05f * f.x;
        v1 = 0.95f * v1 + 0.05f * f.y;
        vmax = fmaxf(vmax, fmaxf(v0, v1));
    }
    if (vmax > 1.0f) sflag = 1;     // benign race: any writer sets 1
    __syncthreads();
    if (sflag) {
        if (threadIdx.x == 0) g_flag[b] = 1;
        __threadfence();
    } else if (threadIdx.x < NOUT) {
        out[b * NOUT + threadIdx.x] = 0.f;   // spike-free: output exactly 0
    }
}

// ---------------- GEMM: C[64000,512] = A'[.,KPAD] x B[512,KPAD]^T (e4m3) ----
// CTA 128x128, 8 warps (2M x 4N), warp tile 64x32. K staged 128 B, dbl-buffered.
// (validated R5/R12 geometry; bf16 epilogue + fused per-batch detection)
#define SMEM_A 0                    // 2 x 16384
#define SMEM_B 32768                // 2 x 16384
#define SM_TOT 65536

__global__ __launch_bounds__(256) void gemm_kernel(const float* __restrict__ x,
                                                   float* __restrict__ out) {
    extern __shared__ char sm[];
    const uint32_t smb = smem_u32(sm);
    const int tid = threadIdx.x, lane = tid & 31, wid = tid >> 5;
    const int wm = wid >> 2, wn = wid & 3;
    const int m0 = blockIdx.y * 128, n0 = blockIdx.x * 128;

    const int crow = tid >> 1;
    const int cgrp = tid & 1;
    const uint32_t cxor = (uint32_t)((crow & 7) << 4);

    const int lrow = (lane & 7) | (((lane >> 3) & 1) << 3);
    const uint32_t lcolh = (uint32_t)((lane >> 4) << 4);
    const uint32_t lxor = (uint32_t)((lrow & 7) << 4);
    const uint32_t aoff0 = (uint32_t)((wm * 64 + lrow) * 128);
    const uint32_t boff0 = (uint32_t)((wn * 32 + lrow) * 128);

    float acc[4][4][4];
#pragma unroll
    for (int i = 0; i < 4; i++)
#pragma unroll
        for (int j = 0; j < 4; j++)
#pragma unroll
            for (int q = 0; q < 4; q++) acc[i][j][q] = 0.f;

    float xs[16];
    uint4 wv[4];

    auto load_stage = [&](int kb) {
        const int nb = kb * 32 + cgrp * 16;
#pragma unroll
        for (int jj = 0; jj < 4; jj++) {
            const int nb4 = nb + 4 * jj;
            if (nb4 + 4 <= NIN) {
                float4 v = __ldg((const float4*)(x + (size_t)(m0 + crow) * NIN + nb4));
                xs[4 * jj] = v.x; xs[4 * jj + 1] = v.y;
                xs[4 * jj + 2] = v.z; xs[4 * jj + 3] = v.w;
            } else {
                xs[4 * jj] = xs[4 * jj + 1] = xs[4 * jj + 2] = xs[4 * jj + 3] = 0.f;
            }
        }
        const uint8_t* wsrc = g_w8 + (size_t)(n0 + crow) * KPAD + kb * 128 + cgrp * 64;
#pragma unroll
        for (int j = 0; j < 4; j++) wv[j] = __ldg((const uint4*)(wsrc + j * 16));
    };
    auto store_stage = [&](int slot) {
        char* ab = sm + SMEM_A + slot * 16384;
        char* bb = sm + SMEM_B + slot * 16384;
        uint32_t p[16];
#pragma unroll
        for (int i = 0; i < 16; i++) {
            float f = xs[i];
            float t1 = fminf(fabsf(f), 1.f);
            float t2 = t1 * t1, t3 = t2 * t1;
            p[i] = pack_e4m3_4(f, t1, t2, t3);
        }
#pragma unroll
        for (int j = 0; j < 4; j++) {
            uint32_t col = (uint32_t)(cgrp * 64 + j * 16);
            *(uint4*)(ab + crow * 128 + (col ^ cxor)) =
                make_uint4(p[4 * j], p[4 * j + 1], p[4 * j + 2], p[4 * j + 3]);
            *(uint4*)(bb + crow * 128 + (col ^ cxor)) = wv[j];
        }
    };

    load_stage(0);
    store_stage(0);

    for (int k = 0; k < NSTG; k++) {
        __syncthreads();
        const int p = k & 1;
        const bool hn = (k + 1 < NSTG);
        if (hn) load_stage(k + 1);

        const uint32_t abuf = smb + SMEM_A + p * 16384;
        const uint32_t bbuf = smb + SMEM_B + p * 16384;
#pragma unroll
        for (int ks = 0; ks < 4; ks++) {
            uint32_t af[4][4], bf[2][4];
            const uint32_t klow = ((uint32_t)(ks * 32) + lcolh) ^ lxor;
#pragma unroll
            for (int mt = 0; mt < 4; mt++)
                ldmx4(af[mt], abuf + aoff0 + (uint32_t)(mt * 2048) + klow);
#pragma unroll
            for (int q = 0; q < 2; q++)
                ldmx4(bf[q], bbuf + boff0 + (uint32_t)(q * 2048) + klow);
#pragma unroll
            for (int mt = 0; mt < 4; mt++)
#pragma unroll
                for (int nt = 0; nt < 4; nt++)
                    mma_e4m3(acc[mt][nt], af[mt],
                             bf[nt >> 1][nt & 1], bf[nt >> 1][(nt & 1) + 2]);
        }
        if (hn) store_stage(p ^ 1);
    }

    // ---- epilogue: dequant + bf16 store ------------------------------------
    const float inv = 1.0f / WSCALE;
#pragma unroll
    for (int mt = 0; mt < 4; mt++) {
        const int r0 = m0 + wm * 64 + mt * 16 + (lane >> 2);
#pragma unroll
        for (int nt = 0; nt < 4; nt++) {
            const int col = n0 + wn * 32 + nt * 8 + 2 * (lane & 3);
            *(__nv_bfloat162*)&g_iin[(size_t)r0 * NHID + col] =
                __floats2bfloat162_rn(acc[mt][nt][0] * inv, acc[mt][nt][1] * inv);
            *(__nv_bfloat162*)&g_iin[(size_t)(r0 + 8) * NHID + col] =
                __floats2bfloat162_rn(acc[mt][nt][2] * inv, acc[mt][nt][3] * inv);
        }
    }

    // ---- fused detection: last CTA covering a batch runs its detect --------
    __threadfence();            // release this CTA's i_in stores
    __syncthreads();            // all threads' stores+fence done
    __shared__ int s_last;
    const int bLo = m0 / 250, bHi = (m0 + 127) / 250;
    for (int b = bLo; b <= bHi && b < B_; b++) {
        if (tid == 0) s_last = (atomicSub(&g_cnt[b], 1) == 1) ? 1 : 0;
        __syncthreads();
        if (s_last) {
            __threadfence();    // acquire: other CTAs' i_in stores now visible
            detect_batch(b, out);
        }
        __syncthreads();
    }
}

// ---------------- scan: heavy path only for flagged batches ------------------
__global__ __launch_bounds__(512) void scan_kernel(const float* __restrict__ w_out,
                                                   float* __restrict__ out) {
    const int b = blockIdx.x, h = threadIdx.x;
    if (g_flag[b] == 0) return;   // zeros already written by fused detect

    const int warp = h >> 5, lane = h & 31;
    __shared__ int s_idx[NHID];
    __shared__ unsigned s_mask[16];

    float v = 0.f, a = 0.f, sprev = 0.f, vout = 0.f, accum = 0.f;
    int cnt = 0;
    const __nv_bfloat16* iin = g_iin + (size_t)b * T_ * NHID + h;
    float c[8];
#pragma unroll
    for (int j = 0; j < 8; j++) c[j] = __bfloat162float(iin[(size_t)j * NHID]);

    for (int t = 0; t < T_; t++) {
        float i1 = c[0];
#pragma unroll
        for (int j = 0; j < 7; j++) c[j] = c[j + 1];
        c[7] = (t + 8 < T_) ? __bfloat162float(iin[(size_t)(t + 8) * NHID]) : 0.f;

        for (int k = 0; k < cnt; k++) i1 += g_wrecT[s_idx[k] * NHID + h];

        v = 0.95f * v + 0.05f * i1 - sprev;
        a = 0.85f * a + 0.15f * sprev;
        const bool spk = (v - (1.0f + 0.05f * a)) > 0.f;

        const int total = __syncthreads_count((int)spk);
        if (total) {  // deterministic compaction of active indices
            const unsigned m = __ballot_sync(0xffffffffu, spk);
            if (lane == 0) s_mask[warp] = m;
            __syncthreads();
            int base = 0;
#pragma unroll
            for (int w = 0; w < 16; w++)
                if (w < warp) base += __popc(s_mask[w]);
            if (spk) s_idx[base + __popc(m & ((1u << lane) - 1u))] = h;
            __syncthreads();
        }

        if (h < NOUT) {
            float io = 0.f;
            for (int k = 0; k < total; k++) io += w_out[h * NHID + s_idx[k]];
            vout = 0.9f * vout + io;
            const float so = vout > 1.f ? 1.f : 0.f;
            vout -= so;
            accum += vout;
        }
        sprev = spk ? 1.f : 0.f;
        cnt = total;
    }
    if (h < NOUT) out[b * NOUT + h] = accum * (1.0f / (float)T_);
}

// ---------------------------------------------------------------------------
extern "C" void kernel_launch(void* const* d_in, const int* in_sizes, int n_in,
                              void* d_out, int out_size) {
    const float* x     = (const float*)d_in[0];
    const float* w_kan = (const float*)d_in[1];
    const float* d1    = (const float*)d_in[2];
    const float* d2    = (const float*)d_in[3];
    const float* d3    = (const float*)d_in[4];
    const float* w_rec = (const float*)d_in[5];
    const float* w_out = (const float*)d_in[6];
    float* out = (float*)d_out;

    cudaFuncSetAttribute(gemm_kernel, cudaFuncAttributeMaxDynamicSharedMemorySize, SM_TOT);

    prep_w8_kernel<<<(NHID * 704 + 255) / 256, 256>>>(w_kan, d1, d2, d3);
    prep_wrect_kernel<<<(NHID * NHID + 255) / 256, 256>>>(w_rec);

    dim3 grid(NHID / 128, (B_ * T_) / 128);  // (4, 500)
    gemm_kernel<<<grid, 256, SM_TOT>>>(x, out);

    scan_kernel<<<B_, NHID>>>(w_out, out);
}

// round 15
// speedup vs baseline: 1.0130x; 1.0130x over previous
#include <cuda_runtime.h>
#include <cuda_bf16.h>
#include <cstdint>

#define B_   256
#define T_   250
#define NIN  700
#define NHID 512
#define NOUT 20
#define KPAD 2816          // 4*NIN = 2800 padded to 128*22 (fp8 bytes)
#define NSTG 22            // K stages of 128 bytes
#define WSCALE 64.0f       // weight pre-scale into e4m3 normal range

// ---------------- scratch (static __device__, no runtime alloc) -------------
__device__ __nv_bfloat16 g_iin[(size_t)B_ * T_ * NHID];  // [B*T][H] bf16
__device__ uint8_t g_w8[(size_t)NHID * KPAD];            // [h][kk] e4m3, kk=4n+v
__device__ float   g_wrecT[NHID * NHID];                 // w_rec^T
__device__ int     g_flag[B_];                           // per-batch spike flag

// ---------------- helpers ----------------------------------------------------
__device__ __forceinline__ uint32_t smem_u32(const void* p) {
    uint32_t a;
    asm("{ .reg .u64 t; cvta.to.shared.u64 t, %1; cvt.u32.u64 %0, t; }"
        : "=r"(a) : "l"(p));
    return a;
}
__device__ __forceinline__ uint32_t pack_e4m3_4(float f0, float f1, float f2, float f3) {
    uint16_t lo, hi;  // d<7:0> = cvt(src2), d<15:8> = cvt(src1)
    asm("cvt.rn.satfinite.e4m3x2.f32 %0, %1, %2;" : "=h"(lo) : "f"(f1), "f"(f0));
    asm("cvt.rn.satfinite.e4m3x2.f32 %0, %1, %2;" : "=h"(hi) : "f"(f3), "f"(f2));
    return (uint32_t)lo | ((uint32_t)hi << 16);   // bytes f0,f1,f2,f3 (k-ascending)
}
__device__ __forceinline__ void ldmx4(uint32_t* r, uint32_t addr) {
    asm volatile("ldmatrix.sync.aligned.m8n8.x4.shared.b16 {%0,%1,%2,%3}, [%4];"
                 : "=r"(r[0]), "=r"(r[1]), "=r"(r[2]), "=r"(r[3]) : "r"(addr));
}
__device__ __forceinline__ void mma_e4m3(float* c, const uint32_t* a,
                                         uint32_t b0, uint32_t b1) {
    asm volatile(
        "mma.sync.aligned.m16n8k32.row.col.f32.e4m3.e4m3.f32 "
        "{%0,%1,%2,%3}, {%4,%5,%6,%7}, {%8,%9}, {%0,%1,%2,%3};"
        : "+f"(c[0]), "+f"(c[1]), "+f"(c[2]), "+f"(c[3])
        : "r"(a[0]), "r"(a[1]), "r"(a[2]), "r"(a[3]), "r"(b0), "r"(b1));
}

// ---------------- merged prep kernel -----------------------------------------
__global__ void prep_kernel(const float* __restrict__ wk, const float* __restrict__ d1,
                            const float* __restrict__ d2, const float* __restrict__ d3,
                            const float* __restrict__ wrec) {
    int i = blockIdx.x * blockDim.x + threadIdx.x;
    if (i < B_) g_flag[i] = 0;
    if (i < NHID * NHID) {
        int h = i % NHID, j = i / NHID;
        g_wrecT[j * NHID + h] = wrec[h * NHID + j];
    }
    if (i < NHID * 704) {
        int h = i / 704, n = i % 704;
        uint32_t w = 0;
        if (n < NIN)
            w = pack_e4m3_4(wk[h * NIN + n] * WSCALE, d1[h * NIN + n] * WSCALE,
                            d2[h * NIN + n] * WSCALE, d3[h * NIN + n] * WSCALE);
        *(uint32_t*)&g_w8[(size_t)h * KPAD + 4 * n] = w;
    }
}

// ---------------- GEMM: C[64000,512] = A'[.,KPAD] x B[512,KPAD]^T (e4m3) ----
// CTA 128x128, 8 warps (2M x 4N), warp tile 64x32. K staged 128 B, dbl-buffered.
// (validated R5/R12 geometry; bf16 epilogue)
#define SMEM_A 0                    // 2 x 16384
#define SMEM_B 32768                // 2 x 16384
#define SM_TOT 65536

__global__ __launch_bounds__(256) void gemm_kernel(const float* __restrict__ x) {
    extern __shared__ char sm[];
    const uint32_t smb = smem_u32(sm);
    const int tid = threadIdx.x, lane = tid & 31, wid = tid >> 5;
    const int wm = wid >> 2, wn = wid & 3;
    const int m0 = blockIdx.y * 128, n0 = blockIdx.x * 128;

    const int crow = tid >> 1;
    const int cgrp = tid & 1;
    const uint32_t cxor = (uint32_t)((crow & 7) << 4);

    const int lrow = (lane & 7) | (((lane >> 3) & 1) << 3);
    const uint32_t lcolh = (uint32_t)((lane >> 4) << 4);
    const uint32_t lxor = (uint32_t)((lrow & 7) << 4);
    const uint32_t aoff0 = (uint32_t)((wm * 64 + lrow) * 128);
    const uint32_t boff0 = (uint32_t)((wn * 32 + lrow) * 128);

    float acc[4][4][4];
#pragma unroll
    for (int i = 0; i < 4; i++)
#pragma unroll
        for (int j = 0; j < 4; j++)
#pragma unroll
            for (int q = 0; q < 4; q++) acc[i][j][q] = 0.f;

    float xs[16];
    uint4 wv[4];

    auto load_stage = [&](int kb) {
        const int nb = kb * 32 + cgrp * 16;
#pragma unroll
        for (int jj = 0; jj < 4; jj++) {
            const int nb4 = nb + 4 * jj;
            if (nb4 + 4 <= NIN) {
                float4 v = __ldg((const float4*)(x + (size_t)(m0 + crow) * NIN + nb4));
                xs[4 * jj] = v.x; xs[4 * jj + 1] = v.y;
                xs[4 * jj + 2] = v.z; xs[4 * jj + 3] = v.w;
            } else {
                xs[4 * jj] = xs[4 * jj + 1] = xs[4 * jj + 2] = xs[4 * jj + 3] = 0.f;
            }
        }
        const uint8_t* wsrc = g_w8 + (size_t)(n0 + crow) * KPAD + kb * 128 + cgrp * 64;
#pragma unroll
        for (int j = 0; j < 4; j++) wv[j] = __ldg((const uint4*)(wsrc + j * 16));
    };
    auto store_stage = [&](int slot) {
        char* ab = sm + SMEM_A + slot * 16384;
        char* bb = sm + SMEM_B + slot * 16384;
        uint32_t p[16];
#pragma unroll
        for (int i = 0; i < 16; i++) {
            float f = xs[i];
            float t1 = fminf(fabsf(f), 1.f);
            float t2 = t1 * t1, t3 = t2 * t1;
            p[i] = pack_e4m3_4(f, t1, t2, t3);
        }
#pragma unroll
        for (int j = 0; j < 4; j++) {
            uint32_t col = (uint32_t)(cgrp * 64 + j * 16);
            *(uint4*)(ab + crow * 128 + (col ^ cxor)) =
                make_uint4(p[4 * j], p[4 * j + 1], p[4 * j + 2], p[4 * j + 3]);
            *(uint4*)(bb + crow * 128 + (col ^ cxor)) = wv[j];
        }
    };

    load_stage(0);
    store_stage(0);

    for (int k = 0; k < NSTG; k++) {
        __syncthreads();
        const int p = k & 1;
        const bool hn = (k + 1 < NSTG);
        if (hn) load_stage(k + 1);

        const uint32_t abuf = smb + SMEM_A + p * 16384;
        const uint32_t bbuf = smb + SMEM_B + p * 16384;
#pragma unroll
        for (int ks = 0; ks < 4; ks++) {
            uint32_t af[4][4], bf[2][4];
            const uint32_t klow = ((uint32_t)(ks * 32) + lcolh) ^ lxor;
#pragma unroll
            for (int mt = 0; mt < 4; mt++)
                ldmx4(af[mt], abuf + aoff0 + (uint32_t)(mt * 2048) + klow);
#pragma unroll
            for (int q = 0; q < 2; q++)
                ldmx4(bf[q], bbuf + boff0 + (uint32_t)(q * 2048) + klow);
            // bf[q]: r0=b0(n-grp0) r1=b0(n-grp1) r2=b1(n-grp0) r3=b1(n-grp1)
#pragma unroll
            for (int mt = 0; mt < 4; mt++)
#pragma unroll
                for (int nt = 0; nt < 4; nt++)
                    mma_e4m3(acc[mt][nt], af[mt],
                             bf[nt >> 1][nt & 1], bf[nt >> 1][(nt & 1) + 2]);
        }
        if (hn) store_stage(p ^ 1);
    }

    // ---- epilogue: dequant + bf16 store ------------------------------------
    const float inv = 1.0f / WSCALE;
#pragma unroll
    for (int mt = 0; mt < 4; mt++) {
        const int r0 = m0 + wm * 64 + mt * 16 + (lane >> 2);
#pragma unroll
        for (int nt = 0; nt < 4; nt++) {
            const int col = n0 + wn * 32 + nt * 8 + 2 * (lane & 3);
            *(__nv_bfloat162*)&g_iin[(size_t)r0 * NHID + col] =
                __floats2bfloat162_rn(acc[mt][nt][0] * inv, acc[mt][nt][1] * inv);
            *(__nv_bfloat162*)&g_iin[(size_t)(r0 + 8) * NHID + col] =
                __floats2bfloat162_rn(acc[mt][nt][2] * inv, acc[mt][nt][3] * inv);
        }
    }
}

// ---------------- spike-free detection (explicit 8-deep prefetch) ------------
// Before the first spike, hidden dynamics are exactly per-(b,h) independent.
// A spike exists iff max_t v_t > 1 for some h. Each thread: 4 adjacent h
// (one uint2 = 2 bf16x2), explicit prefetch ring guarantees 8 loads in flight.
__global__ __launch_bounds__(128) void detect_kernel() {
    const int g = blockIdx.x * 128 + threadIdx.x;   // 0 .. B_*NHID/4-1 (32768)
    const int b = g >> 7, d = g & 127;              // 128 uint2-duos per row
    const uint2* iin = (const uint2*)(g_iin + (size_t)b * T_ * NHID) + d;

    uint2 buf[8];
#pragma unroll
    for (int j = 0; j < 8; j++) buf[j] = __ldg(&iin[(size_t)j * 128]);

    float v0 = 0.f, v1 = 0.f, v2 = 0.f, v3 = 0.f, vmax = -1.f;
#pragma unroll 5
    for (int t = 0; t < T_; t++) {
        const uint2 u = buf[0];
#pragma unroll
        for (int j = 0; j < 7; j++) buf[j] = buf[j + 1];
        buf[7] = (t + 8 < T_) ? __ldg(&iin[(size_t)(t + 8) * 128]) : make_uint2(0u, 0u);

        const float2 f0 = __bfloat1622float2(*(const __nv_bfloat162*)&u.x);
        const float2 f1 = __bfloat1622float2(*(const __nv_bfloat162*)&u.y);
        v0 = 0.95f * v0 + 0.05f * f0.x;
        v1 = 0.95f * v1 + 0.05f * f0.y;
        v2 = 0.95f * v2 + 0.05f * f1.x;
        v3 = 0.95f * v3 + 0.05f * f1.y;
        vmax = fmaxf(vmax, fmaxf(fmaxf(v0, v1), fmaxf(v2, v3)));
    }
    if (vmax > 1.0f) atomicExch(&g_flag[b], 1);
}

// ---------------- scan: 1 CTA / batch (heavy path only when flagged) --------
__global__ __launch_bounds__(512) void scan_kernel(const float* __restrict__ w_out,
                                                   float* __restrict__ out) {
    const int b = blockIdx.x, h = threadIdx.x;

    if (g_flag[b] == 0) {   // spike-free: i_out==0 forever -> output exactly 0
        if (h < NOUT) out[b * NOUT + h] = 0.f;
        return;
    }

    const int warp = h >> 5, lane = h & 31;
    __shared__ int s_idx[NHID];
    __shared__ unsigned s_mask[16];

    float v = 0.f, a = 0.f, sprev = 0.f, vout = 0.f, accum = 0.f;
    int cnt = 0;
    const __nv_bfloat16* iin = g_iin + (size_t)b * T_ * NHID + h;
    float c[8];
#pragma unroll
    for (int j = 0; j < 8; j++) c[j] = __bfloat162float(iin[(size_t)j * NHID]);

    for (int t = 0; t < T_; t++) {
        float i1 = c[0];
#pragma unroll
        for (int j = 0; j < 7; j++) c[j] = c[j + 1];
        c[7] = (t + 8 < T_) ? __bfloat162float(iin[(size_t)(t + 8) * NHID]) : 0.f;

        for (int k = 0; k < cnt; k++) i1 += g_wrecT[s_idx[k] * NHID + h];

        v = 0.95f * v + 0.05f * i1 - sprev;
        a = 0.85f * a + 0.15f * sprev;
        const bool spk = (v - (1.0f + 0.05f * a)) > 0.f;

        const int total = __syncthreads_count((int)spk);
        if (total) {  // deterministic compaction of active indices
            const unsigned m = __ballot_sync(0xffffffffu, spk);
            if (lane == 0) s_mask[warp] = m;
            __syncthreads();
            int base = 0;
#pragma unroll
            for (int w = 0; w < 16; w++)
                if (w < warp) base += __popc(s_mask[w]);
            if (spk) s_idx[base + __popc(m & ((1u << lane) - 1u))] = h;
            __syncthreads();
        }

        if (h < NOUT) {
            float io = 0.f;
            for (int k = 0; k < total; k++) io += w_out[h * NHID + s_idx[k]];
            vout = 0.9f * vout + io;
            const float so = vout > 1.f ? 1.f : 0.f;
            vout -= so;
            accum += vout;
        }
        sprev = spk ? 1.f : 0.f;
        cnt = total;
    }
    if (h < NOUT) out[b * NOUT + h] = accum * (1.0f / (float)T_);
}

// ---------------------------------------------------------------------------
extern "C" void kernel_launch(void* const* d_in, const int* in_sizes, int n_in,
                              void* d_out, int out_size) {
    const float* x     = (const float*)d_in[0];
    const float* w_kan = (const float*)d_in[1];
    const float* d1    = (const float*)d_in[2];
    const float* d2    = (const float*)d_in[3];
    const float* d3    = (const float*)d_in[4];
    const float* w_rec = (const float*)d_in[5];
    const float* w_out = (const float*)d_in[6];
    float* out = (float*)d_out;

    cudaFuncSetAttribute(gemm_kernel, cudaFuncAttributeMaxDynamicSharedMemorySize, SM_TOT);

    prep_kernel<<<(NHID * 704 + 255) / 256, 256>>>(w_kan, d1, d2, d3, w_rec);

    dim3 grid(NHID / 128, (B_ * T_) / 128);  // (4, 500)
    gemm_kernel<<<grid, 256, SM_TOT>>>(x);

    detect_kernel<<<(B_ * NHID / 4) / 128, 128>>>();
    scan_kernel<<<B_, NHID>>>(w_out, out);
}

// round 16
// speedup vs baseline: 1.0346x; 1.0213x over previous
#include <cuda_runtime.h>
#include <cuda_bf16.h>
#include <cstdint>

#define B_   256
#define T_   250
#define NIN  700
#define NHID 512
#define NOUT 20
#define KPAD 2816          // 4*NIN = 2800 padded to 128*22 (fp8 bytes)
#define NSTG 22            // K stages of 128 bytes
#define WSCALE 64.0f       // weight pre-scale into e4m3 normal range

// ---------------- scratch (static __device__, no runtime alloc) -------------
__device__ __nv_bfloat16 g_iin[(size_t)B_ * T_ * NHID];  // [B*T][H] bf16
__device__ uint8_t g_w8[(size_t)NHID * KPAD];            // [h][kk] e4m3, kk=4n+v
__device__ float   g_wrecT[NHID * NHID];                 // w_rec^T

// ---------------- helpers ----------------------------------------------------
__device__ __forceinline__ uint32_t smem_u32(const void* p) {
    uint32_t a;
    asm("{ .reg .u64 t; cvta.to.shared.u64 t, %1; cvt.u32.u64 %0, t; }"
        : "=r"(a) : "l"(p));
    return a;
}
__device__ __forceinline__ uint32_t pack_e4m3_4(float f0, float f1, float f2, float f3) {
    uint16_t lo, hi;  // d<7:0> = cvt(src2), d<15:8> = cvt(src1)
    asm("cvt.rn.satfinite.e4m3x2.f32 %0, %1, %2;" : "=h"(lo) : "f"(f1), "f"(f0));
    asm("cvt.rn.satfinite.e4m3x2.f32 %0, %1, %2;" : "=h"(hi) : "f"(f3), "f"(f2));
    return (uint32_t)lo | ((uint32_t)hi << 16);   // bytes f0,f1,f2,f3 (k-ascending)
}
__device__ __forceinline__ void ldmx4(uint32_t* r, uint32_t addr) {
    asm volatile("ldmatrix.sync.aligned.m8n8.x4.shared.b16 {%0,%1,%2,%3}, [%4];"
                 : "=r"(r[0]), "=r"(r[1]), "=r"(r[2]), "=r"(r[3]) : "r"(addr));
}
__device__ __forceinline__ void mma_e4m3(float* c, const uint32_t* a,
                                         uint32_t b0, uint32_t b1) {
    asm volatile(
        "mma.sync.aligned.m16n8k32.row.col.f32.e4m3.e4m3.f32 "
        "{%0,%1,%2,%3}, {%4,%5,%6,%7}, {%8,%9}, {%0,%1,%2,%3};"
        : "+f"(c[0]), "+f"(c[1]), "+f"(c[2]), "+f"(c[3])
        : "r"(a[0]), "r"(a[1]), "r"(a[2]), "r"(a[3]), "r"(b0), "r"(b1));
}

// ---------------- merged prep kernel -----------------------------------------
__global__ void prep_kernel(const float* __restrict__ wk, const float* __restrict__ d1,
                            const float* __restrict__ d2, const float* __restrict__ d3,
                            const float* __restrict__ wrec) {
    int i = blockIdx.x * blockDim.x + threadIdx.x;
    if (i < NHID * NHID) {
        int h = i % NHID, j = i / NHID;
        g_wrecT[j * NHID + h] = wrec[h * NHID + j];
    }
    if (i < NHID * 704) {
        int h = i / 704, n = i % 704;
        uint32_t w = 0;
        if (n < NIN)
            w = pack_e4m3_4(wk[h * NIN + n] * WSCALE, d1[h * NIN + n] * WSCALE,
                            d2[h * NIN + n] * WSCALE, d3[h * NIN + n] * WSCALE);
        *(uint32_t*)&g_w8[(size_t)h * KPAD + 4 * n] = w;
    }
}

// ---------------- GEMM: C[64000,512] = A'[.,KPAD] x B[512,KPAD]^T (e4m3) ----
// CTA 128x128, 8 warps (2M x 4N), warp tile 64x32. K staged 128 B, dbl-buffered.
// (validated R5/R12 geometry; bf16 epilogue)
#define SMEM_A 0                    // 2 x 16384
#define SMEM_B 32768                // 2 x 16384
#define SM_TOT 65536

__global__ __launch_bounds__(256) void gemm_kernel(const float* __restrict__ x) {
    extern __shared__ char sm[];
    const uint32_t smb = smem_u32(sm);
    const int tid = threadIdx.x, lane = tid & 31, wid = tid >> 5;
    const int wm = wid >> 2, wn = wid & 3;
    const int m0 = blockIdx.y * 128, n0 = blockIdx.x * 128;

    const int crow = tid >> 1;
    const int cgrp = tid & 1;
    const uint32_t cxor = (uint32_t)((crow & 7) << 4);

    const int lrow = (lane & 7) | (((lane >> 3) & 1) << 3);
    const uint32_t lcolh = (uint32_t)((lane >> 4) << 4);
    const uint32_t lxor = (uint32_t)((lrow & 7) << 4);
    const uint32_t aoff0 = (uint32_t)((wm * 64 + lrow) * 128);
    const uint32_t boff0 = (uint32_t)((wn * 32 + lrow) * 128);

    float acc[4][4][4];
#pragma unroll
    for (int i = 0; i < 4; i++)
#pragma unroll
        for (int j = 0; j < 4; j++)
#pragma unroll
            for (int q = 0; q < 4; q++) acc[i][j][q] = 0.f;

    float xs[16];
    uint4 wv[4];

    auto load_stage = [&](int kb) {
        const int nb = kb * 32 + cgrp * 16;
#pragma unroll
        for (int jj = 0; jj < 4; jj++) {
            const int nb4 = nb + 4 * jj;
            if (nb4 + 4 <= NIN) {
                float4 v = __ldg((const float4*)(x + (size_t)(m0 + crow) * NIN + nb4));
                xs[4 * jj] = v.x; xs[4 * jj + 1] = v.y;
                xs[4 * jj + 2] = v.z; xs[4 * jj + 3] = v.w;
            } else {
                xs[4 * jj] = xs[4 * jj + 1] = xs[4 * jj + 2] = xs[4 * jj + 3] = 0.f;
            }
        }
        const uint8_t* wsrc = g_w8 + (size_t)(n0 + crow) * KPAD + kb * 128 + cgrp * 64;
#pragma unroll
        for (int j = 0; j < 4; j++) wv[j] = __ldg((const uint4*)(wsrc + j * 16));
    };
    auto store_stage = [&](int slot) {
        char* ab = sm + SMEM_A + slot * 16384;
        char* bb = sm + SMEM_B + slot * 16384;
        uint32_t p[16];
#pragma unroll
        for (int i = 0; i < 16; i++) {
            float f = xs[i];
            float t1 = fminf(fabsf(f), 1.f);
            float t2 = t1 * t1, t3 = t2 * t1;
            p[i] = pack_e4m3_4(f, t1, t2, t3);
        }
#pragma unroll
        for (int j = 0; j < 4; j++) {
            uint32_t col = (uint32_t)(cgrp * 64 + j * 16);
            *(uint4*)(ab + crow * 128 + (col ^ cxor)) =
                make_uint4(p[4 * j], p[4 * j + 1], p[4 * j + 2], p[4 * j + 3]);
            *(uint4*)(bb + crow * 128 + (col ^ cxor)) = wv[j];
        }
    };

    load_stage(0);
    store_stage(0);

    for (int k = 0; k < NSTG; k++) {
        __syncthreads();
        const int p = k & 1;
        const bool hn = (k + 1 < NSTG);
        if (hn) load_stage(k + 1);

        const uint32_t abuf = smb + SMEM_A + p * 16384;
        const uint32_t bbuf = smb + SMEM_B + p * 16384;
#pragma unroll
        for (int ks = 0; ks < 4; ks++) {
            uint32_t af[4][4], bf[2][4];
            const uint32_t klow = ((uint32_t)(ks * 32) + lcolh) ^ lxor;
#pragma unroll
            for (int mt = 0; mt < 4; mt++)
                ldmx4(af[mt], abuf + aoff0 + (uint32_t)(mt * 2048) + klow);
#pragma unroll
            for (int q = 0; q < 2; q++)
                ldmx4(bf[q], bbuf + boff0 + (uint32_t)(q * 2048) + klow);
            // bf[q]: r0=b0(n-grp0) r1=b0(n-grp1) r2=b1(n-grp0) r3=b1(n-grp1)
#pragma unroll
            for (int mt = 0; mt < 4; mt++)
#pragma unroll
                for (int nt = 0; nt < 4; nt++)
                    mma_e4m3(acc[mt][nt], af[mt],
                             bf[nt >> 1][nt & 1], bf[nt >> 1][(nt & 1) + 2]);
        }
        if (hn) store_stage(p ^ 1);
    }

    // ---- epilogue: dequant + bf16 store ------------------------------------
    const float inv = 1.0f / WSCALE;
#pragma unroll
    for (int mt = 0; mt < 4; mt++) {
        const int r0 = m0 + wm * 64 + mt * 16 + (lane >> 2);
#pragma unroll
        for (int nt = 0; nt < 4; nt++) {
            const int col = n0 + wn * 32 + nt * 8 + 2 * (lane & 3);
            *(__nv_bfloat162*)&g_iin[(size_t)r0 * NHID + col] =
                __floats2bfloat162_rn(acc[mt][nt][0] * inv, acc[mt][nt][1] * inv);
            *(__nv_bfloat162*)&g_iin[(size_t)(r0 + 8) * NHID + col] =
                __floats2bfloat162_rn(acc[mt][nt][2] * inv, acc[mt][nt][3] * inv);
        }
    }
}

// ---------------- fused detect + scan: 1 CTA / batch -------------------------
// Phase 1 (threads 0-255, R12-proven detect math): before the first spike,
// hidden dynamics are exactly per-(b,h) independent; a spike exists iff
// max_t v_t > 1 for some h. Phase 2: heavy sequential scan only if flagged.
__global__ __launch_bounds__(512) void scan_kernel(const float* __restrict__ w_out,
                                                   float* __restrict__ out) {
    const int b = blockIdx.x, h = threadIdx.x;
    const int warp = h >> 5, lane = h & 31;

    // ---- phase 1: barrier-free spike detection ----
    float vmax = -1.f;
    if (h < 256) {
        const __nv_bfloat162* di =
            (const __nv_bfloat162*)(g_iin + (size_t)b * T_ * NHID) + h;
        float v0 = 0.f, v1 = 0.f;
#pragma unroll 10
        for (int t = 0; t < T_; t++) {
            float2 f = __bfloat1622float2(__ldg(&di[(size_t)t * (NHID / 2)]));
            v0 = 0.95f * v0 + 0.05f * f.x;
            v1 = 0.95f * v1 + 0.05f * f.y;
            vmax = fmaxf(vmax, fmaxf(v0, v1));
        }
    }
    const int any = __syncthreads_count(vmax > 1.0f);
    if (any == 0) {   // spike-free: i_out==0 forever -> output exactly 0
        if (h < NOUT) out[b * NOUT + h] = 0.f;
        return;
    }

    // ---- phase 2: exact sequential dynamics (proven heavy path) ----
    __shared__ int s_idx[NHID];
    __shared__ unsigned s_mask[16];

    float v = 0.f, a = 0.f, sprev = 0.f, vout = 0.f, accum = 0.f;
    int cnt = 0;
    const __nv_bfloat16* iin = g_iin + (size_t)b * T_ * NHID + h;
    float c[8];
#pragma unroll
    for (int j = 0; j < 8; j++) c[j] = __bfloat162float(iin[(size_t)j * NHID]);

    for (int t = 0; t < T_; t++) {
        float i1 = c[0];
#pragma unroll
        for (int j = 0; j < 7; j++) c[j] = c[j + 1];
        c[7] = (t + 8 < T_) ? __bfloat162float(iin[(size_t)(t + 8) * NHID]) : 0.f;

        for (int k = 0; k < cnt; k++) i1 += g_wrecT[s_idx[k] * NHID + h];

        v = 0.95f * v + 0.05f * i1 - sprev;
        a = 0.85f * a + 0.15f * sprev;
        const bool spk = (v - (1.0f + 0.05f * a)) > 0.f;

        const int total = __syncthreads_count((int)spk);
        if (total) {  // deterministic compaction of active indices
            const unsigned m = __ballot_sync(0xffffffffu, spk);
            if (lane == 0) s_mask[warp] = m;
            __syncthreads();
            int base = 0;
#pragma unroll
            for (int w = 0; w < 16; w++)
                if (w < warp) base += __popc(s_mask[w]);
            if (spk) s_idx[base + __popc(m & ((1u << lane) - 1u))] = h;
            __syncthreads();
        }

        if (h < NOUT) {
            float io = 0.f;
            for (int k = 0; k < total; k++) io += w_out[h * NHID + s_idx[k]];
            vout = 0.9f * vout + io;
            const float so = vout > 1.f ? 1.f : 0.f;
            vout -= so;
            accum += vout;
        }
        sprev = spk ? 1.f : 0.f;
        cnt = total;
    }
    if (h < NOUT) out[b * NOUT + h] = accum * (1.0f / (float)T_);
}

// ---------------------------------------------------------------------------
extern "C" void kernel_launch(void* const* d_in, const int* in_sizes, int n_in,
                              void* d_out, int out_size) {
    const float* x     = (const float*)d_in[0];
    const float* w_kan = (const float*)d_in[1];
    const float* d1    = (const float*)d_in[2];
    const float* d2    = (const float*)d_in[3];
    const float* d3    = (const float*)d_in[4];
    const float* w_rec = (const float*)d_in[5];
    const float* w_out = (const float*)d_in[6];
    float* out = (float*)d_out;

    cudaFuncSetAttribute(gemm_kernel, cudaFuncAttributeMaxDynamicSharedMemorySize, SM_TOT);

    prep_kernel<<<(NHID * 704 + 255) / 256, 256>>>(w_kan, d1, d2, d3, w_rec);

    dim3 grid(NHID / 128, (B_ * T_) / 128);  // (4, 500)
    gemm_kernel<<<grid, 256, SM_TOT>>>(x);

    scan_kernel<<<B_, NHID>>>(w_out, out);
}